// round 15
// baseline (speedup 1.0000x reference)
#include <cuda_runtime.h>
#include <cuda_bf16.h>
#include <mma.h>
#include <cstdint>

using namespace nvcuda;

#define N_AG 4096
#define M_CL 256
#define KD 32
#define PF 640             /* padded feature count (5*128) */
#define KSPLIT 32
#define NSPL (N_AG / KSPLIT)   /* 128 n per split */
#define NCH (NSPL / 32)        /* 4 chunks */
#define RGRP 4                 /* reduce groups (stage-1 outputs) */
#define CNT_BLKS 512
#define W_EPS 1e-6f

#define ALA 72    /* A smem leading dim (bf16) */
#define ALB 136   /* B smem leading dim (bf16) */
#define TG_SMEM ((2 * 32 * ALA + 2 * 2 * 32 * ALB) * 2)  /* 43520 bytes */

// static scratch (no allocations allowed)
__device__ __align__(16) __nv_bfloat16 g_Whi[(size_t)N_AG * M_CL];  // masked, [n][m]
__device__ __align__(16) __nv_bfloat16 g_Phi[(size_t)N_AG * PF];    // [n][f]
__device__ __align__(16) __nv_bfloat16 g_Plo[(size_t)N_AG * PF];
__device__ __align__(16) float g_part[(size_t)KSPLIT * M_CL * PF];
__device__ __align__(16) float g_S4[RGRP][(size_t)M_CL * PF];
__device__ float g_cnt[CNT_BLKS * M_CL];

// ---------------------------------------------------------------------------
// Kernel A: batched 32x32 SPD solve fused with feature build (bf16 hi/lo out).
// ---------------------------------------------------------------------------
__global__ void __launch_bounds__(256) solve_feat_kernel(const float* __restrict__ A,
                                                         const float* __restrict__ rhs) {
  __shared__ __align__(16) float prow[8][36];
  int t = threadIdx.x, wid = t >> 5, lane = t & 31;
  int n = blockIdx.x * 8 + wid;
  const float* Ar = A + (size_t)n * (KD * KD) + lane * KD;

  float a[KD];
#pragma unroll
  for (int q = 0; q < 8; q++) {
    float4 v4 = *reinterpret_cast<const float4*>(Ar + 4 * q);
    a[4 * q + 0] = v4.x; a[4 * q + 1] = v4.y;
    a[4 * q + 2] = v4.z; a[4 * q + 3] = v4.w;
  }
  float b = rhs[n * KD + lane];
  float diag = 1.0f;
  float* pr = prow[wid];

#pragma unroll
  for (int j = 0; j < KD; j++) {
    if (lane == j) {
#pragma unroll
      for (int q = 0; q < 8; q++)
        if (4 * q + 3 >= j)
          *reinterpret_cast<float4*>(&pr[4 * q]) =
              make_float4(a[4 * q], a[4 * q + 1], a[4 * q + 2], a[4 * q + 3]);
      pr[32] = b;
      diag = a[j];
    }
    __syncwarp();
    float pd  = pr[j];
    float bp  = pr[32];
    float inv = 1.0f / pd;
    float f   = (lane == j) ? 0.0f : a[j] * inv;
#pragma unroll
    for (int q = 0; q < 8; q++)
      if (4 * q + 3 >= j) {
        float4 pv = *reinterpret_cast<const float4*>(&pr[4 * q]);
        a[4 * q + 0] = fmaf(-f, pv.x, a[4 * q + 0]);
        a[4 * q + 1] = fmaf(-f, pv.y, a[4 * q + 1]);
        a[4 * q + 2] = fmaf(-f, pv.z, a[4 * q + 2]);
        a[4 * q + 3] = fmaf(-f, pv.w, a[4 * q + 3]);
      }
    b = fmaf(-f, bp, b);
    __syncwarp();
  }
  float x = b / diag;

  pr[lane] = x;
  __syncwarp();
  float xv[KD];
#pragma unroll
  for (int q = 0; q < 8; q++) {
    float4 v4 = *reinterpret_cast<const float4*>(&pr[4 * q]);
    xv[4 * q + 0] = v4.x; xv[4 * q + 1] = v4.y;
    xv[4 * q + 2] = v4.z; xv[4 * q + 3] = v4.w;
  }
  __nv_bfloat16* Ph = g_Phi + (size_t)n * PF;
  __nv_bfloat16* Pl = g_Plo + (size_t)n * PF;
  {
    __nv_bfloat16 h = __float2bfloat16(x);
    Ph[lane] = h;
    Pl[lane] = __float2bfloat16(x - __bfloat162float(h));
  }
  int base = KD;
#pragma unroll
  for (int k = 0; k < KD; k++) {
    if (lane >= k) {
      float val = xv[k] * x;
      __nv_bfloat16 h = __float2bfloat16(val);
      Ph[base + lane - k] = h;
      Pl[base + lane - k] = __float2bfloat16(val - __bfloat162float(h));
    }
    base += KD - k;
  }
  const __nv_bfloat16 bz = __float2bfloat16(0.0f);
  if (lane == 0) { Ph[560] = __float2bfloat16(1.0f); Pl[560] = bz; }
  for (int f = 561 + lane; f < PF; f += 32) { Ph[f] = bz; Pl[f] = bz; }
}

// ---------------------------------------------------------------------------
// prepW + cnt (fused): one pass over W -> masked bf16 hi + per-block count.
// 512 blocks x 8 n-rows (3.5 CTAs/SM full wave; was 128 blocks = 0.86/SM).
// ---------------------------------------------------------------------------
__global__ void __launch_bounds__(256) prepw_cnt_kernel(const float* __restrict__ W) {
  __shared__ float sc[4][256];
  int t = threadIdx.x;
  int rg = t >> 6, m4 = (t & 63) * 4;
  int nb = blockIdx.x * 8 + rg * 2;
  float4 c = make_float4(0.f, 0.f, 0.f, 0.f);
#pragma unroll
  for (int i = 0; i < 2; i++) {
    int n = nb + i;
    float4 w = *reinterpret_cast<const float4*>(&W[(size_t)n * M_CL + m4]);
    c.x += (w.x >= W_EPS) ? 1.0f : 0.0f;
    c.y += (w.y >= W_EPS) ? 1.0f : 0.0f;
    c.z += (w.z >= W_EPS) ? 1.0f : 0.0f;
    c.w += (w.w >= W_EPS) ? 1.0f : 0.0f;
    w.x = (w.x >= W_EPS) ? w.x : 0.0f;
    w.y = (w.y >= W_EPS) ? w.y : 0.0f;
    w.z = (w.z >= W_EPS) ? w.z : 0.0f;
    w.w = (w.w >= W_EPS) ? w.w : 0.0f;
    __nv_bfloat162 h01, h23;
    h01.x = __float2bfloat16(w.x); h01.y = __float2bfloat16(w.y);
    h23.x = __float2bfloat16(w.z); h23.y = __float2bfloat16(w.w);
    *reinterpret_cast<__nv_bfloat162*>(&g_Whi[(size_t)n * M_CL + m4])     = h01;
    *reinterpret_cast<__nv_bfloat162*>(&g_Whi[(size_t)n * M_CL + m4 + 2]) = h23;
  }
  *reinterpret_cast<float4*>(&sc[rg][m4]) = c;
  __syncthreads();
  if (t < 64) {
    int m = t * 4;
    float4 a0 = *reinterpret_cast<float4*>(&sc[0][m]);
    float4 a1 = *reinterpret_cast<float4*>(&sc[1][m]);
    float4 a2 = *reinterpret_cast<float4*>(&sc[2][m]);
    float4 a3 = *reinterpret_cast<float4*>(&sc[3][m]);
    float4 o = make_float4(a0.x + a1.x + a2.x + a3.x, a0.y + a1.y + a2.y + a3.y,
                           a0.z + a1.z + a2.z + a3.z, a0.w + a1.w + a2.w + a3.w);
    *reinterpret_cast<float4*>(&g_cnt[blockIdx.x * M_CL + m]) = o;
  }
}

// ---------------------------------------------------------------------------
// tgemm: bf16 wmma, double-buffered, 4 CTA/SM cap.  TWO passes:
//   P1: a x bh,  P2: a x bl   (W single-precision-bf16; P split hi/lo)
// ---------------------------------------------------------------------------
__global__ void __launch_bounds__(128, 4) tgemm_kernel() {
  extern __shared__ __align__(16) char smem[];
  __nv_bfloat16* sA  = reinterpret_cast<__nv_bfloat16*>(smem);
  __nv_bfloat16* sBh = sA + 2 * 32 * ALA;
  __nv_bfloat16* sBl = sBh + 2 * 32 * ALB;

  int t = threadIdx.x, wid = t >> 5;
  int m0 = blockIdx.x * 64;
  int f0 = blockIdx.y * 128;
  int nb = blockIdx.z * NSPL;
  int row = t >> 2;                        // 0..31
  int cA  = (t & 3) * 16;
  int cB  = (t & 3) * 32;

  wmma::fragment<wmma::accumulator, 16, 16, 16, float> acc[4][2];
#pragma unroll
  for (int i = 0; i < 4; i++)
#pragma unroll
    for (int j = 0; j < 2; j++) wmma::fill_fragment(acc[i][j], 0.0f);

  auto load_chunk = [&](int ch, int st) {
    int n0 = nb + ch * 32;
    __nv_bfloat16* a  = sA  + st * 32 * ALA;
    __nv_bfloat16* bh = sBh + st * 32 * ALB;
    __nv_bfloat16* bl = sBl + st * 32 * ALB;
    const uint4* wh = reinterpret_cast<const uint4*>(
        &g_Whi[(size_t)(n0 + row) * M_CL + m0 + cA]);
    *reinterpret_cast<uint4*>(&a[row * ALA + cA])     = wh[0];
    *reinterpret_cast<uint4*>(&a[row * ALA + cA + 8]) = wh[1];
    const uint4* ph = reinterpret_cast<const uint4*>(
        &g_Phi[(size_t)(n0 + row) * PF + f0 + cB]);
    const uint4* pl = reinterpret_cast<const uint4*>(
        &g_Plo[(size_t)(n0 + row) * PF + f0 + cB]);
#pragma unroll
    for (int u = 0; u < 4; u++) {
      *reinterpret_cast<uint4*>(&bh[row * ALB + cB + u * 8]) = ph[u];
      *reinterpret_cast<uint4*>(&bl[row * ALB + cB + u * 8]) = pl[u];
    }
  };

  load_chunk(0, 0);
  __syncthreads();

  for (int ch = 0; ch < NCH; ch++) {
    int st = ch & 1;
    if (ch + 1 < NCH) load_chunk(ch + 1, st ^ 1);
    __nv_bfloat16* a0  = sA  + st * 32 * ALA;
    __nv_bfloat16* bh0 = sBh + st * 32 * ALB;
    __nv_bfloat16* bl0 = sBl + st * 32 * ALB;
#pragma unroll
    for (int kk = 0; kk < 2; kk++) {
      wmma::fragment<wmma::matrix_a, 16, 16, 16, __nv_bfloat16, wmma::col_major> af[4];
      wmma::fragment<wmma::matrix_b, 16, 16, 16, __nv_bfloat16, wmma::row_major> bf[2];
#pragma unroll
      for (int i = 0; i < 4; i++)
        wmma::load_matrix_sync(af[i], &a0[kk * 16 * ALA + i * 16], ALA);
#pragma unroll
      for (int j = 0; j < 2; j++)
        wmma::load_matrix_sync(bf[j], &bh0[kk * 16 * ALB + wid * 32 + j * 16], ALB);
#pragma unroll
      for (int i = 0; i < 4; i++)
#pragma unroll
        for (int j = 0; j < 2; j++) wmma::mma_sync(acc[i][j], af[i], bf[j], acc[i][j]);
#pragma unroll
      for (int j = 0; j < 2; j++)
        wmma::load_matrix_sync(bf[j], &bl0[kk * 16 * ALB + wid * 32 + j * 16], ALB);
#pragma unroll
      for (int i = 0; i < 4; i++)
#pragma unroll
        for (int j = 0; j < 2; j++) wmma::mma_sync(acc[i][j], af[i], bf[j], acc[i][j]);
    }
    __syncthreads();
  }

  float* pbase = g_part + (size_t)blockIdx.z * M_CL * PF;
#pragma unroll
  for (int i = 0; i < 4; i++)
#pragma unroll
    for (int j = 0; j < 2; j++)
      wmma::store_matrix_sync(
          &pbase[(size_t)(m0 + i * 16) * PF + f0 + wid * 32 + j * 16],
          acc[i][j], PF, wmma::mem_row_major);
}

// ---------------------------------------------------------------------------
// reduce stage 1: grid (160, 4).  Block (bx, g) sums K-splits [8g, 8g+8)
// for its feature-quad range -> g_S4[g].  640 blocks, MLP=8.
// ---------------------------------------------------------------------------
__global__ void __launch_bounds__(256) reduce_kernel() {
  int idx = (blockIdx.x * 256 + threadIdx.x) * 4;
  int g = blockIdx.y;
  float4 acc = make_float4(0.f, 0.f, 0.f, 0.f);
  float4 v[8];
#pragma unroll
  for (int u = 0; u < 8; u++)
    v[u] = *reinterpret_cast<const float4*>(
        &g_part[(size_t)(g * 8 + u) * M_CL * PF + idx]);
#pragma unroll
  for (int u = 0; u < 8; u++) {
    acc.x += v[u].x; acc.y += v[u].y; acc.z += v[u].z; acc.w += v[u].w;
  }
  *reinterpret_cast<float4*>(&g_S4[g][idx]) = acc;
}

// ---------------------------------------------------------------------------
// final3: one block per m.  Sum 4 reduce groups, Omega^2 triangle-dot inline.
// ---------------------------------------------------------------------------
__global__ void __launch_bounds__(256) final3_kernel(const float* __restrict__ Omega,
                                                     float* __restrict__ out) {
  __shared__ float sfeat[PF];
  __shared__ float sO[KD * KD];
  __shared__ float red[256];
  __shared__ float s_tr, s_usq;

  int m = blockIdx.x, t = threadIdx.x;

  for (int f = t; f < PF; f += 256) {
    float a = 0.0f;
#pragma unroll
    for (int g = 0; g < RGRP; g++) a += g_S4[g][m * PF + f];
    sfeat[f] = a;
  }
  for (int e = t; e < KD * KD; e += 256) sO[e] = Omega[(size_t)m * KD * KD + e];
  __syncthreads();

  float tr = 0.0f;
  for (int ft = t; ft < 528; ft += 256) {
    float disc = 4225.0f - 8.0f * (float)ft;
    int k = (int)((65.0f - sqrtf(disc)) * 0.5f);
    int b0 = k * KD - (k * (k - 1)) / 2;
    if (ft < b0) { k--; b0 = k * KD - (k * (k - 1)) / 2; }
    else if (ft >= b0 + (KD - k)) { k++; b0 = k * KD - (k * (k - 1)) / 2; }
    int l = k + (ft - b0);
    float g = 0.0f;
#pragma unroll
    for (int q = 0; q < KD; q++) g = fmaf(sO[k * KD + q], sO[l * KD + q], g);
    float mult = (k == l) ? 1.0f : 2.0f;
    tr = fmaf(mult * g, sfeat[32 + ft], tr);
  }
  red[t] = tr;
  __syncthreads();
  for (int s = 128; s > 0; s >>= 1) { if (t < s) red[t] += red[t + s]; __syncthreads(); }
  if (t == 0) s_tr = red[0];
  __syncthreads();

  float up = 0.0f;
  if (t < KD) {
    float u = 0.0f;
#pragma unroll
    for (int q = 0; q < KD; q++) u = fmaf(sO[t * KD + q], sfeat[q], u);
    up = u * u;
  }
  red[t] = up;
  __syncthreads();
  for (int s = 128; s > 0; s >>= 1) { if (t < s) red[t] += red[t + s]; __syncthreads(); }
  if (t == 0) s_usq = red[0];
  __syncthreads();

  // count: 512 partials, 2 per thread
  float c = g_cnt[t * M_CL + m] + g_cnt[(t + 256) * M_CL + m];
  red[t] = c;
  __syncthreads();
  for (int s = 128; s > 0; s >>= 1) { if (t < s) red[t] += red[t + s]; __syncthreads(); }

  if (t == 0) {
    float Z   = fmaxf(sfeat[560], 1e-30f);
    float psi = s_tr / Z - s_usq / (Z * Z);
    out[m] = (red[0] >= 1.5f) ? psi : 0.0f;
  }
}

// ---------------------------------------------------------------------------
extern "C" void kernel_launch(void* const* d_in, const int* in_sizes, int n_in,
                              void* d_out, int out_size) {
  const float* W            = (const float*)d_in[0];  // (N, M)
  const float* mu_s         = (const float*)d_in[1];  // (N, K)
  const float* omega_child  = (const float*)d_in[2];  // (N, K, K)
  const float* omega_parent = (const float*)d_in[3];  // (M, K, K)
  float* out = (float*)d_out;                         // (M,)

  static int smem_set = 0;
  if (!smem_set) {
    cudaFuncSetAttribute(tgemm_kernel, cudaFuncAttributeMaxDynamicSharedMemorySize,
                         TG_SMEM);
    smem_set = 1;
  }

  solve_feat_kernel<<<N_AG / 8, 256>>>(omega_child, mu_s);
  prepw_cnt_kernel<<<CNT_BLKS, 256>>>(W);
  tgemm_kernel<<<dim3(M_CL / 64, PF / 128, KSPLIT), 128, TG_SMEM>>>();
  reduce_kernel<<<dim3((M_CL * PF) / (4 * 256), RGRP), 256>>>();
  final3_kernel<<<M_CL, 256>>>(omega_parent, out);
}

// round 16
// speedup vs baseline: 1.0463x; 1.0463x over previous
#include <cuda_runtime.h>
#include <cuda_bf16.h>
#include <mma.h>
#include <cstdint>

using namespace nvcuda;

#define N_AG 4096
#define M_CL 256
#define KD 32
#define PF 640             /* padded feature count (5*128) */
#define KSPLIT 16
#define NSPL (N_AG / KSPLIT)   /* 256 n per split */
#define NCH (NSPL / 32)        /* 8 chunks */
#define RGRP 4                 /* reduce groups */
#define RPG (KSPLIT / RGRP)    /* 4 splits per group */
#define CNT_BLKS 512
#define W_EPS 1e-6f

#define ALA 72    /* smem leading dim for 64-wide bf16 tiles */
#define TG_SMEM ((2 * 32 * ALA * 3) * 2)   /* A + Bh + Bl, 2 stages: 27648 B */

// static scratch (no allocations allowed)
__device__ __align__(16) __nv_bfloat16 g_Whi[(size_t)N_AG * M_CL];  // masked, [n][m]
__device__ __align__(16) __nv_bfloat16 g_Phi[(size_t)N_AG * PF];    // [n][f]
__device__ __align__(16) __nv_bfloat16 g_Plo[(size_t)N_AG * PF];
__device__ __align__(16) float g_part[(size_t)KSPLIT * M_CL * PF];
__device__ __align__(16) float g_S4[RGRP][(size_t)M_CL * PF];
__device__ float g_cnt[CNT_BLKS * M_CL];

// ---------------------------------------------------------------------------
// Kernel A: batched 32x32 SPD solve fused with feature build (bf16 hi/lo out).
// ---------------------------------------------------------------------------
__global__ void __launch_bounds__(256) solve_feat_kernel(const float* __restrict__ A,
                                                         const float* __restrict__ rhs) {
  __shared__ __align__(16) float prow[8][36];
  int t = threadIdx.x, wid = t >> 5, lane = t & 31;
  int n = blockIdx.x * 8 + wid;
  const float* Ar = A + (size_t)n * (KD * KD) + lane * KD;

  float a[KD];
#pragma unroll
  for (int q = 0; q < 8; q++) {
    float4 v4 = *reinterpret_cast<const float4*>(Ar + 4 * q);
    a[4 * q + 0] = v4.x; a[4 * q + 1] = v4.y;
    a[4 * q + 2] = v4.z; a[4 * q + 3] = v4.w;
  }
  float b = rhs[n * KD + lane];
  float diag = 1.0f;
  float* pr = prow[wid];

#pragma unroll
  for (int j = 0; j < KD; j++) {
    if (lane == j) {
#pragma unroll
      for (int q = 0; q < 8; q++)
        if (4 * q + 3 >= j)
          *reinterpret_cast<float4*>(&pr[4 * q]) =
              make_float4(a[4 * q], a[4 * q + 1], a[4 * q + 2], a[4 * q + 3]);
      pr[32] = b;
      diag = a[j];
    }
    __syncwarp();
    float pd  = pr[j];
    float bp  = pr[32];
    float inv = 1.0f / pd;
    float f   = (lane == j) ? 0.0f : a[j] * inv;
#pragma unroll
    for (int q = 0; q < 8; q++)
      if (4 * q + 3 >= j) {
        float4 pv = *reinterpret_cast<const float4*>(&pr[4 * q]);
        a[4 * q + 0] = fmaf(-f, pv.x, a[4 * q + 0]);
        a[4 * q + 1] = fmaf(-f, pv.y, a[4 * q + 1]);
        a[4 * q + 2] = fmaf(-f, pv.z, a[4 * q + 2]);
        a[4 * q + 3] = fmaf(-f, pv.w, a[4 * q + 3]);
      }
    b = fmaf(-f, bp, b);
    __syncwarp();
  }
  float x = b / diag;

  pr[lane] = x;
  __syncwarp();
  float xv[KD];
#pragma unroll
  for (int q = 0; q < 8; q++) {
    float4 v4 = *reinterpret_cast<const float4*>(&pr[4 * q]);
    xv[4 * q + 0] = v4.x; xv[4 * q + 1] = v4.y;
    xv[4 * q + 2] = v4.z; xv[4 * q + 3] = v4.w;
  }
  __nv_bfloat16* Ph = g_Phi + (size_t)n * PF;
  __nv_bfloat16* Pl = g_Plo + (size_t)n * PF;
  {
    __nv_bfloat16 h = __float2bfloat16(x);
    Ph[lane] = h;
    Pl[lane] = __float2bfloat16(x - __bfloat162float(h));
  }
  int base = KD;
#pragma unroll
  for (int k = 0; k < KD; k++) {
    if (lane >= k) {
      float val = xv[k] * x;
      __nv_bfloat16 h = __float2bfloat16(val);
      Ph[base + lane - k] = h;
      Pl[base + lane - k] = __float2bfloat16(val - __bfloat162float(h));
    }
    base += KD - k;
  }
  const __nv_bfloat16 bz = __float2bfloat16(0.0f);
  if (lane == 0) { Ph[560] = __float2bfloat16(1.0f); Pl[560] = bz; }
  for (int f = 561 + lane; f < PF; f += 32) { Ph[f] = bz; Pl[f] = bz; }
}

// ---------------------------------------------------------------------------
// prepW + cnt (fused): 512 blocks x 8 n-rows.
// ---------------------------------------------------------------------------
__global__ void __launch_bounds__(256) prepw_cnt_kernel(const float* __restrict__ W) {
  __shared__ float sc[4][256];
  int t = threadIdx.x;
  int rg = t >> 6, m4 = (t & 63) * 4;
  int nb = blockIdx.x * 8 + rg * 2;
  float4 c = make_float4(0.f, 0.f, 0.f, 0.f);
#pragma unroll
  for (int i = 0; i < 2; i++) {
    int n = nb + i;
    float4 w = *reinterpret_cast<const float4*>(&W[(size_t)n * M_CL + m4]);
    c.x += (w.x >= W_EPS) ? 1.0f : 0.0f;
    c.y += (w.y >= W_EPS) ? 1.0f : 0.0f;
    c.z += (w.z >= W_EPS) ? 1.0f : 0.0f;
    c.w += (w.w >= W_EPS) ? 1.0f : 0.0f;
    w.x = (w.x >= W_EPS) ? w.x : 0.0f;
    w.y = (w.y >= W_EPS) ? w.y : 0.0f;
    w.z = (w.z >= W_EPS) ? w.z : 0.0f;
    w.w = (w.w >= W_EPS) ? w.w : 0.0f;
    __nv_bfloat162 h01, h23;
    h01.x = __float2bfloat16(w.x); h01.y = __float2bfloat16(w.y);
    h23.x = __float2bfloat16(w.z); h23.y = __float2bfloat16(w.w);
    *reinterpret_cast<__nv_bfloat162*>(&g_Whi[(size_t)n * M_CL + m4])     = h01;
    *reinterpret_cast<__nv_bfloat162*>(&g_Whi[(size_t)n * M_CL + m4 + 2]) = h23;
  }
  *reinterpret_cast<float4*>(&sc[rg][m4]) = c;
  __syncthreads();
  if (t < 64) {
    int m = t * 4;
    float4 a0 = *reinterpret_cast<float4*>(&sc[0][m]);
    float4 a1 = *reinterpret_cast<float4*>(&sc[1][m]);
    float4 a2 = *reinterpret_cast<float4*>(&sc[2][m]);
    float4 a3 = *reinterpret_cast<float4*>(&sc[3][m]);
    float4 o = make_float4(a0.x + a1.x + a2.x + a3.x, a0.y + a1.y + a2.y + a3.y,
                           a0.z + a1.z + a2.z + a3.z, a0.w + a1.w + a2.w + a3.w);
    *reinterpret_cast<float4*>(&g_cnt[blockIdx.x * M_CL + m]) = o;
  }
}

// ---------------------------------------------------------------------------
// tgemm: bf16 wmma, 64m x 64f tile, double-buffered, 6 CTA/SM target.
// Warp tile 64m x 16f (acc 4x1); A-frag loaded one-at-a-time to keep regs
// low.  grid (4, 10, 16) = 640 CTAs, NCH = 8 chunks of 32 n.
// ---------------------------------------------------------------------------
__global__ void __launch_bounds__(128, 6) tgemm_kernel() {
  extern __shared__ __align__(16) char smem[];
  __nv_bfloat16* sA  = reinterpret_cast<__nv_bfloat16*>(smem);          // 2*32*ALA
  __nv_bfloat16* sBh = sA + 2 * 32 * ALA;
  __nv_bfloat16* sBl = sBh + 2 * 32 * ALA;

  int t = threadIdx.x, wid = t >> 5;
  int m0 = blockIdx.x * 64;
  int f0 = blockIdx.y * 64;
  int nb = blockIdx.z * NSPL;
  int row = t >> 2;                        // 0..31
  int cc  = (t & 3) * 16;                  // 16 bf16 (2 uint4) per thread

  wmma::fragment<wmma::accumulator, 16, 16, 16, float> acc[4];
#pragma unroll
  for (int i = 0; i < 4; i++) wmma::fill_fragment(acc[i], 0.0f);

  auto load_chunk = [&](int ch, int st) {
    int n0 = nb + ch * 32;
    __nv_bfloat16* a  = sA  + st * 32 * ALA;
    __nv_bfloat16* bh = sBh + st * 32 * ALA;
    __nv_bfloat16* bl = sBl + st * 32 * ALA;
    const uint4* wh = reinterpret_cast<const uint4*>(
        &g_Whi[(size_t)(n0 + row) * M_CL + m0 + cc]);
    *reinterpret_cast<uint4*>(&a[row * ALA + cc])     = wh[0];
    *reinterpret_cast<uint4*>(&a[row * ALA + cc + 8]) = wh[1];
    const uint4* ph = reinterpret_cast<const uint4*>(
        &g_Phi[(size_t)(n0 + row) * PF + f0 + cc]);
    const uint4* pl = reinterpret_cast<const uint4*>(
        &g_Plo[(size_t)(n0 + row) * PF + f0 + cc]);
    *reinterpret_cast<uint4*>(&bh[row * ALA + cc])     = ph[0];
    *reinterpret_cast<uint4*>(&bh[row * ALA + cc + 8]) = ph[1];
    *reinterpret_cast<uint4*>(&bl[row * ALA + cc])     = pl[0];
    *reinterpret_cast<uint4*>(&bl[row * ALA + cc + 8]) = pl[1];
  };

  load_chunk(0, 0);
  __syncthreads();

  for (int ch = 0; ch < NCH; ch++) {
    int st = ch & 1;
    if (ch + 1 < NCH) load_chunk(ch + 1, st ^ 1);
    __nv_bfloat16* a0  = sA  + st * 32 * ALA;
    __nv_bfloat16* bh0 = sBh + st * 32 * ALA;
    __nv_bfloat16* bl0 = sBl + st * 32 * ALA;
#pragma unroll
    for (int kk = 0; kk < 2; kk++) {
      wmma::fragment<wmma::matrix_b, 16, 16, 16, __nv_bfloat16, wmma::row_major> bf;
      // pass 1: a x bh
      wmma::load_matrix_sync(bf, &bh0[kk * 16 * ALA + wid * 16], ALA);
#pragma unroll
      for (int i = 0; i < 4; i++) {
        wmma::fragment<wmma::matrix_a, 16, 16, 16, __nv_bfloat16, wmma::col_major> af;
        wmma::load_matrix_sync(af, &a0[kk * 16 * ALA + i * 16], ALA);
        wmma::mma_sync(acc[i], af, bf, acc[i]);
      }
      // pass 2: a x bl
      wmma::load_matrix_sync(bf, &bl0[kk * 16 * ALA + wid * 16], ALA);
#pragma unroll
      for (int i = 0; i < 4; i++) {
        wmma::fragment<wmma::matrix_a, 16, 16, 16, __nv_bfloat16, wmma::col_major> af;
        wmma::load_matrix_sync(af, &a0[kk * 16 * ALA + i * 16], ALA);
        wmma::mma_sync(acc[i], af, bf, acc[i]);
      }
    }
    __syncthreads();
  }

  float* pbase = g_part + (size_t)blockIdx.z * M_CL * PF;
#pragma unroll
  for (int i = 0; i < 4; i++)
    wmma::store_matrix_sync(
        &pbase[(size_t)(m0 + i * 16) * PF + f0 + wid * 16],
        acc[i], PF, wmma::mem_row_major);
}

// ---------------------------------------------------------------------------
// reduce stage 1: grid (160, 4).  Block (bx, g) sums K-splits [4g, 4g+4)
// for its feature-quad range -> g_S4[g].  640 blocks, MLP=4.
// ---------------------------------------------------------------------------
__global__ void __launch_bounds__(256) reduce_kernel() {
  int idx = (blockIdx.x * 256 + threadIdx.x) * 4;
  int g = blockIdx.y;
  float4 acc = make_float4(0.f, 0.f, 0.f, 0.f);
  float4 v[RPG];
#pragma unroll
  for (int u = 0; u < RPG; u++)
    v[u] = *reinterpret_cast<const float4*>(
        &g_part[(size_t)(g * RPG + u) * M_CL * PF + idx]);
#pragma unroll
  for (int u = 0; u < RPG; u++) {
    acc.x += v[u].x; acc.y += v[u].y; acc.z += v[u].z; acc.w += v[u].w;
  }
  *reinterpret_cast<float4*>(&g_S4[g][idx]) = acc;
}

// ---------------------------------------------------------------------------
// final3: one block per m.  Sum 4 reduce groups, Omega^2 triangle-dot inline.
// ---------------------------------------------------------------------------
__global__ void __launch_bounds__(256) final3_kernel(const float* __restrict__ Omega,
                                                     float* __restrict__ out) {
  __shared__ float sfeat[PF];
  __shared__ float sO[KD * KD];
  __shared__ float red[256];
  __shared__ float s_tr, s_usq;

  int m = blockIdx.x, t = threadIdx.x;

  for (int f = t; f < PF; f += 256) {
    float a = 0.0f;
#pragma unroll
    for (int g = 0; g < RGRP; g++) a += g_S4[g][m * PF + f];
    sfeat[f] = a;
  }
  for (int e = t; e < KD * KD; e += 256) sO[e] = Omega[(size_t)m * KD * KD + e];
  __syncthreads();

  float tr = 0.0f;
  for (int ft = t; ft < 528; ft += 256) {
    float disc = 4225.0f - 8.0f * (float)ft;
    int k = (int)((65.0f - sqrtf(disc)) * 0.5f);
    int b0 = k * KD - (k * (k - 1)) / 2;
    if (ft < b0) { k--; b0 = k * KD - (k * (k - 1)) / 2; }
    else if (ft >= b0 + (KD - k)) { k++; b0 = k * KD - (k * (k - 1)) / 2; }
    int l = k + (ft - b0);
    float g = 0.0f;
#pragma unroll
    for (int q = 0; q < KD; q++) g = fmaf(sO[k * KD + q], sO[l * KD + q], g);
    float mult = (k == l) ? 1.0f : 2.0f;
    tr = fmaf(mult * g, sfeat[32 + ft], tr);
  }
  red[t] = tr;
  __syncthreads();
  for (int s = 128; s > 0; s >>= 1) { if (t < s) red[t] += red[t + s]; __syncthreads(); }
  if (t == 0) s_tr = red[0];
  __syncthreads();

  float up = 0.0f;
  if (t < KD) {
    float u = 0.0f;
#pragma unroll
    for (int q = 0; q < KD; q++) u = fmaf(sO[t * KD + q], sfeat[q], u);
    up = u * u;
  }
  red[t] = up;
  __syncthreads();
  for (int s = 128; s > 0; s >>= 1) { if (t < s) red[t] += red[t + s]; __syncthreads(); }
  if (t == 0) s_usq = red[0];
  __syncthreads();

  float c = g_cnt[t * M_CL + m] + g_cnt[(t + 256) * M_CL + m];
  red[t] = c;
  __syncthreads();
  for (int s = 128; s > 0; s >>= 1) { if (t < s) red[t] += red[t + s]; __syncthreads(); }

  if (t == 0) {
    float Z   = fmaxf(sfeat[560], 1e-30f);
    float psi = s_tr / Z - s_usq / (Z * Z);
    out[m] = (red[0] >= 1.5f) ? psi : 0.0f;
  }
}

// ---------------------------------------------------------------------------
extern "C" void kernel_launch(void* const* d_in, const int* in_sizes, int n_in,
                              void* d_out, int out_size) {
  const float* W            = (const float*)d_in[0];  // (N, M)
  const float* mu_s         = (const float*)d_in[1];  // (N, K)
  const float* omega_child  = (const float*)d_in[2];  // (N, K, K)
  const float* omega_parent = (const float*)d_in[3];  // (M, K, K)
  float* out = (float*)d_out;                         // (M,)

  static int smem_set = 0;
  if (!smem_set) {
    cudaFuncSetAttribute(tgemm_kernel, cudaFuncAttributeMaxDynamicSharedMemorySize,
                         TG_SMEM);
    smem_set = 1;
  }

  solve_feat_kernel<<<N_AG / 8, 256>>>(omega_child, mu_s);
  prepw_cnt_kernel<<<CNT_BLKS, 256>>>(W);
  tgemm_kernel<<<dim3(M_CL / 64, PF / 64, KSPLIT), 128, TG_SMEM>>>();
  reduce_kernel<<<dim3((M_CL * PF) / (4 * 256), RGRP), 256>>>();
  final3_kernel<<<M_CL, 256>>>(omega_parent, out);
}

// round 17
// speedup vs baseline: 1.0758x; 1.0282x over previous
#include <cuda_runtime.h>
#include <cuda_bf16.h>
#include <mma.h>
#include <cstdint>

using namespace nvcuda;

#define N_AG 4096
#define M_CL 256
#define KD 32
#define PF 640             /* padded feature count (5*128) */
#define KSPLIT 16
#define NSPL (N_AG / KSPLIT)   /* 256 n per split */
#define NCH (NSPL / 32)        /* 8 chunks */
#define CNT_BLKS 512
#define W_EPS 1e-6f

#define ALA 72    /* smem leading dim for 64-wide bf16 tiles */
#define TG_SMEM ((2 * 32 * ALA * 3) * 2)   /* A + Bh + Bl, 2 stages: 27648 B */

// static scratch (no allocations allowed)
__device__ __align__(16) __nv_bfloat16 g_Whi[(size_t)N_AG * M_CL];  // masked, [n][m]
__device__ __align__(16) __nv_bfloat16 g_Phi[(size_t)N_AG * PF];    // [n][f]
__device__ __align__(16) __nv_bfloat16 g_Plo[(size_t)N_AG * PF];
__device__ __align__(16) float g_part[(size_t)KSPLIT * M_CL * PF];
__device__ __align__(16) float g_S[(size_t)M_CL * PF];
__device__ float g_cnt[CNT_BLKS * M_CL];

// ---------------------------------------------------------------------------
// Fused front kernel, grid 1024:
//   blocks [0, 512):    batched 32x32 SPD solve + feature build (bf16 hi/lo)
//   blocks [512, 1024): W -> masked bf16 + count
// Heterogeneous co-scheduling: latency-bound solve warps and bandwidth-bound
// prep warps share SMs and fill each other's issue gaps.
// ---------------------------------------------------------------------------
__global__ void __launch_bounds__(256) front_kernel(const float* __restrict__ A,
                                                    const float* __restrict__ rhs,
                                                    const float* __restrict__ W) {
  if (blockIdx.x < 512) {
    // ---------------- solve + features ----------------
    __shared__ __align__(16) float prow[8][36];
    int t = threadIdx.x, wid = t >> 5, lane = t & 31;
    int n = blockIdx.x * 8 + wid;
    const float* Ar = A + (size_t)n * (KD * KD) + lane * KD;

    float a[KD];
#pragma unroll
    for (int q = 0; q < 8; q++) {
      float4 v4 = *reinterpret_cast<const float4*>(Ar + 4 * q);
      a[4 * q + 0] = v4.x; a[4 * q + 1] = v4.y;
      a[4 * q + 2] = v4.z; a[4 * q + 3] = v4.w;
    }
    float b = rhs[n * KD + lane];
    float diag = 1.0f;
    float* pr = prow[wid];

#pragma unroll
    for (int j = 0; j < KD; j++) {
      if (lane == j) {
#pragma unroll
        for (int q = 0; q < 8; q++)
          if (4 * q + 3 >= j)
            *reinterpret_cast<float4*>(&pr[4 * q]) =
                make_float4(a[4 * q], a[4 * q + 1], a[4 * q + 2], a[4 * q + 3]);
        pr[32] = b;
        diag = a[j];
      }
      __syncwarp();
      float pd  = pr[j];
      float bp  = pr[32];
      float inv = 1.0f / pd;
      float f   = (lane == j) ? 0.0f : a[j] * inv;
#pragma unroll
      for (int q = 0; q < 8; q++)
        if (4 * q + 3 >= j) {
          float4 pv = *reinterpret_cast<const float4*>(&pr[4 * q]);
          a[4 * q + 0] = fmaf(-f, pv.x, a[4 * q + 0]);
          a[4 * q + 1] = fmaf(-f, pv.y, a[4 * q + 1]);
          a[4 * q + 2] = fmaf(-f, pv.z, a[4 * q + 2]);
          a[4 * q + 3] = fmaf(-f, pv.w, a[4 * q + 3]);
        }
      b = fmaf(-f, bp, b);
      __syncwarp();
    }
    float x = b / diag;

    pr[lane] = x;
    __syncwarp();
    float xv[KD];
#pragma unroll
    for (int q = 0; q < 8; q++) {
      float4 v4 = *reinterpret_cast<const float4*>(&pr[4 * q]);
      xv[4 * q + 0] = v4.x; xv[4 * q + 1] = v4.y;
      xv[4 * q + 2] = v4.z; xv[4 * q + 3] = v4.w;
    }
    __nv_bfloat16* Ph = g_Phi + (size_t)n * PF;
    __nv_bfloat16* Pl = g_Plo + (size_t)n * PF;
    {
      __nv_bfloat16 h = __float2bfloat16(x);
      Ph[lane] = h;
      Pl[lane] = __float2bfloat16(x - __bfloat162float(h));
    }
    int base = KD;
#pragma unroll
    for (int k = 0; k < KD; k++) {
      if (lane >= k) {
        float val = xv[k] * x;
        __nv_bfloat16 h = __float2bfloat16(val);
        Ph[base + lane - k] = h;
        Pl[base + lane - k] = __float2bfloat16(val - __bfloat162float(h));
      }
      base += KD - k;
    }
    const __nv_bfloat16 bz = __float2bfloat16(0.0f);
    if (lane == 0) { Ph[560] = __float2bfloat16(1.0f); Pl[560] = bz; }
    for (int f = 561 + lane; f < PF; f += 32) { Ph[f] = bz; Pl[f] = bz; }
  } else {
    // ---------------- W prep + count ----------------
    __shared__ float sc[4][256];
    int bx = blockIdx.x - 512;
    int t = threadIdx.x;
    int rg = t >> 6, m4 = (t & 63) * 4;
    int nb = bx * 8 + rg * 2;
    float4 c = make_float4(0.f, 0.f, 0.f, 0.f);
#pragma unroll
    for (int i = 0; i < 2; i++) {
      int n = nb + i;
      float4 w = *reinterpret_cast<const float4*>(&W[(size_t)n * M_CL + m4]);
      c.x += (w.x >= W_EPS) ? 1.0f : 0.0f;
      c.y += (w.y >= W_EPS) ? 1.0f : 0.0f;
      c.z += (w.z >= W_EPS) ? 1.0f : 0.0f;
      c.w += (w.w >= W_EPS) ? 1.0f : 0.0f;
      w.x = (w.x >= W_EPS) ? w.x : 0.0f;
      w.y = (w.y >= W_EPS) ? w.y : 0.0f;
      w.z = (w.z >= W_EPS) ? w.z : 0.0f;
      w.w = (w.w >= W_EPS) ? w.w : 0.0f;
      __nv_bfloat162 h01, h23;
      h01.x = __float2bfloat16(w.x); h01.y = __float2bfloat16(w.y);
      h23.x = __float2bfloat16(w.z); h23.y = __float2bfloat16(w.w);
      *reinterpret_cast<__nv_bfloat162*>(&g_Whi[(size_t)n * M_CL + m4])     = h01;
      *reinterpret_cast<__nv_bfloat162*>(&g_Whi[(size_t)n * M_CL + m4 + 2]) = h23;
    }
    *reinterpret_cast<float4*>(&sc[rg][m4]) = c;
    __syncthreads();
    if (t < 64) {
      int m = t * 4;
      float4 a0 = *reinterpret_cast<float4*>(&sc[0][m]);
      float4 a1 = *reinterpret_cast<float4*>(&sc[1][m]);
      float4 a2 = *reinterpret_cast<float4*>(&sc[2][m]);
      float4 a3 = *reinterpret_cast<float4*>(&sc[3][m]);
      float4 o = make_float4(a0.x + a1.x + a2.x + a3.x, a0.y + a1.y + a2.y + a3.y,
                             a0.z + a1.z + a2.z + a3.z, a0.w + a1.w + a2.w + a3.w);
      *reinterpret_cast<float4*>(&g_cnt[bx * M_CL + m]) = o;
    }
  }
}

// ---------------------------------------------------------------------------
// tgemm: bf16 wmma, 64m x 64f tile, double-buffered, 6 CTA/SM.
// Warp tile 64m x 16f (acc 4x1); grid (4, 10, 16) = 640 CTAs, NCH = 8.
// ---------------------------------------------------------------------------
__global__ void __launch_bounds__(128, 6) tgemm_kernel() {
  extern __shared__ __align__(16) char smem[];
  __nv_bfloat16* sA  = reinterpret_cast<__nv_bfloat16*>(smem);
  __nv_bfloat16* sBh = sA + 2 * 32 * ALA;
  __nv_bfloat16* sBl = sBh + 2 * 32 * ALA;

  int t = threadIdx.x, wid = t >> 5;
  int m0 = blockIdx.x * 64;
  int f0 = blockIdx.y * 64;
  int nb = blockIdx.z * NSPL;
  int row = t >> 2;
  int cc  = (t & 3) * 16;

  wmma::fragment<wmma::accumulator, 16, 16, 16, float> acc[4];
#pragma unroll
  for (int i = 0; i < 4; i++) wmma::fill_fragment(acc[i], 0.0f);

  auto load_chunk = [&](int ch, int st) {
    int n0 = nb + ch * 32;
    __nv_bfloat16* a  = sA  + st * 32 * ALA;
    __nv_bfloat16* bh = sBh + st * 32 * ALA;
    __nv_bfloat16* bl = sBl + st * 32 * ALA;
    const uint4* wh = reinterpret_cast<const uint4*>(
        &g_Whi[(size_t)(n0 + row) * M_CL + m0 + cc]);
    *reinterpret_cast<uint4*>(&a[row * ALA + cc])     = wh[0];
    *reinterpret_cast<uint4*>(&a[row * ALA + cc + 8]) = wh[1];
    const uint4* ph = reinterpret_cast<const uint4*>(
        &g_Phi[(size_t)(n0 + row) * PF + f0 + cc]);
    const uint4* pl = reinterpret_cast<const uint4*>(
        &g_Plo[(size_t)(n0 + row) * PF + f0 + cc]);
    *reinterpret_cast<uint4*>(&bh[row * ALA + cc])     = ph[0];
    *reinterpret_cast<uint4*>(&bh[row * ALA + cc + 8]) = ph[1];
    *reinterpret_cast<uint4*>(&bl[row * ALA + cc])     = pl[0];
    *reinterpret_cast<uint4*>(&bl[row * ALA + cc + 8]) = pl[1];
  };

  load_chunk(0, 0);
  __syncthreads();

  for (int ch = 0; ch < NCH; ch++) {
    int st = ch & 1;
    if (ch + 1 < NCH) load_chunk(ch + 1, st ^ 1);
    __nv_bfloat16* a0  = sA  + st * 32 * ALA;
    __nv_bfloat16* bh0 = sBh + st * 32 * ALA;
    __nv_bfloat16* bl0 = sBl + st * 32 * ALA;
#pragma unroll
    for (int kk = 0; kk < 2; kk++) {
      wmma::fragment<wmma::matrix_b, 16, 16, 16, __nv_bfloat16, wmma::row_major> bf;
      wmma::load_matrix_sync(bf, &bh0[kk * 16 * ALA + wid * 16], ALA);
#pragma unroll
      for (int i = 0; i < 4; i++) {
        wmma::fragment<wmma::matrix_a, 16, 16, 16, __nv_bfloat16, wmma::col_major> af;
        wmma::load_matrix_sync(af, &a0[kk * 16 * ALA + i * 16], ALA);
        wmma::mma_sync(acc[i], af, bf, acc[i]);
      }
      wmma::load_matrix_sync(bf, &bl0[kk * 16 * ALA + wid * 16], ALA);
#pragma unroll
      for (int i = 0; i < 4; i++) {
        wmma::fragment<wmma::matrix_a, 16, 16, 16, __nv_bfloat16, wmma::col_major> af;
        wmma::load_matrix_sync(af, &a0[kk * 16 * ALA + i * 16], ALA);
        wmma::mma_sync(acc[i], af, bf, acc[i]);
      }
    }
    __syncthreads();
  }

  float* pbase = g_part + (size_t)blockIdx.z * M_CL * PF;
#pragma unroll
  for (int i = 0; i < 4; i++)
    wmma::store_matrix_sync(
        &pbase[(size_t)(m0 + i * 16) * PF + f0 + wid * 16],
        acc[i], PF, wmma::mem_row_major);
}

// ---------------------------------------------------------------------------
// reduce: single stage, one thread per (m,f) SCALAR.  grid 640 x 256:
// 16 independent coalesced loads per thread (MLP=16) over 10.5 MB.
// ---------------------------------------------------------------------------
__global__ void __launch_bounds__(256) reduce_kernel() {
  int idx = blockIdx.x * 256 + threadIdx.x;
  float v[KSPLIT];
#pragma unroll
  for (int ks = 0; ks < KSPLIT; ks++)
    v[ks] = g_part[(size_t)ks * M_CL * PF + idx];
  float a = 0.0f;
#pragma unroll
  for (int ks = 0; ks < KSPLIT; ks++) a += v[ks];
  g_S[idx] = a;
}

// ---------------------------------------------------------------------------
// final3: one block per m.  Omega^2 triangle-dot inline.
// ---------------------------------------------------------------------------
__global__ void __launch_bounds__(256) final3_kernel(const float* __restrict__ Omega,
                                                     float* __restrict__ out) {
  __shared__ float sfeat[PF];
  __shared__ float sO[KD * KD];
  __shared__ float red[256];
  __shared__ float s_tr, s_usq;

  int m = blockIdx.x, t = threadIdx.x;

  for (int f = t; f < PF; f += 256) sfeat[f] = g_S[m * PF + f];
  for (int e = t; e < KD * KD; e += 256) sO[e] = Omega[(size_t)m * KD * KD + e];
  __syncthreads();

  float tr = 0.0f;
  for (int ft = t; ft < 528; ft += 256) {
    float disc = 4225.0f - 8.0f * (float)ft;
    int k = (int)((65.0f - sqrtf(disc)) * 0.5f);
    int b0 = k * KD - (k * (k - 1)) / 2;
    if (ft < b0) { k--; b0 = k * KD - (k * (k - 1)) / 2; }
    else if (ft >= b0 + (KD - k)) { k++; b0 = k * KD - (k * (k - 1)) / 2; }
    int l = k + (ft - b0);
    float g = 0.0f;
#pragma unroll
    for (int q = 0; q < KD; q++) g = fmaf(sO[k * KD + q], sO[l * KD + q], g);
    float mult = (k == l) ? 1.0f : 2.0f;
    tr = fmaf(mult * g, sfeat[32 + ft], tr);
  }
  red[t] = tr;
  __syncthreads();
  for (int s = 128; s > 0; s >>= 1) { if (t < s) red[t] += red[t + s]; __syncthreads(); }
  if (t == 0) s_tr = red[0];
  __syncthreads();

  float up = 0.0f;
  if (t < KD) {
    float u = 0.0f;
#pragma unroll
    for (int q = 0; q < KD; q++) u = fmaf(sO[t * KD + q], sfeat[q], u);
    up = u * u;
  }
  red[t] = up;
  __syncthreads();
  for (int s = 128; s > 0; s >>= 1) { if (t < s) red[t] += red[t + s]; __syncthreads(); }
  if (t == 0) s_usq = red[0];
  __syncthreads();

  float c = g_cnt[t * M_CL + m] + g_cnt[(t + 256) * M_CL + m];
  red[t] = c;
  __syncthreads();
  for (int s = 128; s > 0; s >>= 1) { if (t < s) red[t] += red[t + s]; __syncthreads(); }

  if (t == 0) {
    float Z   = fmaxf(sfeat[560], 1e-30f);
    float psi = s_tr / Z - s_usq / (Z * Z);
    out[m] = (red[0] >= 1.5f) ? psi : 0.0f;
  }
}

// ---------------------------------------------------------------------------
extern "C" void kernel_launch(void* const* d_in, const int* in_sizes, int n_in,
                              void* d_out, int out_size) {
  const float* W            = (const float*)d_in[0];  // (N, M)
  const float* mu_s         = (const float*)d_in[1];  // (N, K)
  const float* omega_child  = (const float*)d_in[2];  // (N, K, K)
  const float* omega_parent = (const float*)d_in[3];  // (M, K, K)
  float* out = (float*)d_out;                         // (M,)

  static int smem_set = 0;
  if (!smem_set) {
    cudaFuncSetAttribute(tgemm_kernel, cudaFuncAttributeMaxDynamicSharedMemorySize,
                         TG_SMEM);
    smem_set = 1;
  }

  front_kernel<<<1024, 256>>>(omega_child, mu_s, W);
  tgemm_kernel<<<dim3(M_CL / 64, PF / 64, KSPLIT), 128, TG_SMEM>>>();
  reduce_kernel<<<(M_CL * PF) / 256, 256>>>();
  final3_kernel<<<M_CL, 256>>>(omega_parent, out);
}